// round 14
// baseline (speedup 1.0000x reference)
#include <cuda_runtime.h>

#define WIN 11
#define PAD 5
#define TX 32
#define TY 32
#define INX 42
#define INY 42
#define IMG_H 512
#define IMG_W 512
#define NT 256

#define C1V 1.0e-4f
#define C2V 9.0e-4f
#define EPS2 1.0e-12f
#define A_CHARB 0.3f
#define A_SSIM  0.6f

// Normalized 11-tap Gaussian (sigma=1.5), double-precision derived.
#define W0 0.00102838f
#define W1 0.00759876f
#define W2 0.03600078f
#define W3 0.10936070f
#define W4 0.21300554f
#define W5 0.26601173f

// s_h4 row stride in float4 units — odd => H-pass STS.128 row-walk conflict-free.
#define HSTRIDE 37

typedef unsigned long long u64;

__device__ __forceinline__ float gw(int k) {   // compile-time k -> FFMA immediate
    switch (k) {
        case 0:  return W0; case 1:  return W1; case 2:  return W2;
        case 3:  return W3; case 4:  return W4; case 5:  return W5;
        case 6:  return W4; case 7:  return W3; case 8:  return W2;
        case 9:  return W1; default: return W0;
    }
}

__device__ __forceinline__ u64 gwp(int k) {    // packed (w,w) compile-time constant
    unsigned u = __float_as_uint(gw(k));
    return ((u64)u << 32) | (u64)u;
}

__device__ __forceinline__ void fma2(u64& acc, u64 a, u64 b) {
    asm("fma.rn.f32x2 %0, %1, %2, %0;" : "+l"(acc) : "l"(a), "l"(b));
}

__device__ __forceinline__ float2 unpack2(u64 v) {
    float2 t;
    asm("mov.b64 {%0, %1}, %2;" : "=f"(t.x), "=f"(t.y) : "l"(v));
    return t;
}

struct __align__(16) U64x2 { u64 a, b; };      // one LDS.128 -> two f32x2 operands

__global__ __launch_bounds__(NT, 5)
void ssim_loss_kernel(const float* __restrict__ pred,
                      const float* __restrict__ targ,
                      float* __restrict__ out) {
    __shared__ float2 s_in[INY][47];                     // (x,y); cols 42..46 zero pad
    __shared__ __align__(16) float4 s_h4[INY][HSTRIDE];  // (hx, hy, hss, hxy)

    const int tid = threadIdx.x;
    const int tile_x = blockIdx.x * TX;
    const int tile_y = blockIdx.y * TY;
    const int plane = blockIdx.z;

    const float* __restrict__ px = pred + (size_t)plane * IMG_H * IMG_W;
    const float* __restrict__ py = targ + (size_t)plane * IMG_H * IMG_W;
    float* __restrict__ po = out + (size_t)plane * IMG_H * IMG_W;

    // ---- pad-zero cols 42..46 (H window over-read region) ----
    if (tid < INY * 5) {
        int r = tid / 5, c = 42 + tid % 5;
        s_in[r][c] = make_float2(0.f, 0.f);
    }

    // ---- halo load, aligned float4; c12-major so STS lanes walk rows (<=2-way) ----
    {
        const int g0 = tile_x - 8;                   // 16B-aligned (tile_x % 32 == 0)
        #pragma unroll
        for (int rd = 0; rd < 2; rd++) {
            int unit = rd * NT + tid;
            if (unit < INY * 12) {
                int c12 = unit / INY, r = unit - c12 * INY;
                int gr = tile_y + r - PAD;
                int gc0 = g0 + 4 * c12;
                float4 vx = make_float4(0.f, 0.f, 0.f, 0.f);
                float4 vy = vx;
                if (gr >= 0 && gr < IMG_H && gc0 >= 0 && gc0 < IMG_W) {
                    size_t off = ((size_t)gr * IMG_W + gc0) >> 2;
                    vx = ((const float4*)px)[off];
                    vy = ((const float4*)py)[off];
                }
                int l0 = 4 * c12 - 3;                // local col of vx.x
                float xs[4] = {vx.x, vx.y, vx.z, vx.w};
                float ys[4] = {vy.x, vy.y, vy.z, vy.w};
                #pragma unroll
                for (int q = 0; q < 4; q++) {
                    int l = l0 + q;
                    if (l >= 0 && l < INX)
                        s_in[r][l] = make_float2(xs[q], ys[q]);
                }
            }
        }
    }
    __syncthreads();

    // ---- H-pass: 42 rows x 6-col chunks = 252 units, one per thread (scalar, imm weights) ----
    if (tid < INY * 6) {
        const int r  = tid % INY;
        const int c0 = (tid / INY) * 6;              // 0,6,...,30

        float ax[6], ay[6], ass[6], axy[6];
        #pragma unroll
        for (int j = 0; j < 6; j++) { ax[j]=0.f; ay[j]=0.f; ass[j]=0.f; axy[j]=0.f; }

        #pragma unroll
        for (int i = 0; i < 16; i++) {
            float2 v = s_in[r][c0 + i];
            float ss = fmaf(v.y, v.y, v.x * v.x);
            float xy = v.x * v.y;
            #pragma unroll
            for (int j = 0; j < 6; j++) {
                const int k = i - j;
                if (k >= 0 && k < WIN) {
                    const float wk = gw(k);
                    ax[j]  = fmaf(wk, v.x, ax[j]);
                    ay[j]  = fmaf(wk, v.y, ay[j]);
                    ass[j] = fmaf(wk, ss,  ass[j]);
                    axy[j] = fmaf(wk, xy,  axy[j]);
                }
            }
        }
        #pragma unroll
        for (int j = 0; j < 6; j++)
            s_h4[r][c0 + j] = make_float4(ax[j], ay[j], ass[j], axy[j]);
    }
    __syncthreads();

    // ---- V-pass: f32x2 on register pairs straight out of LDS.128 ----
    const int c  = tid & (TX - 1);
    const int r0 = (tid >> 5) * 4;                   // 0,4,...,28

    u64 a01[4], a23[4];
    #pragma unroll
    for (int j = 0; j < 4; j++) { a01[j] = 0ull; a23[j] = 0ull; }

    const U64x2* __restrict__ hp = reinterpret_cast<const U64x2*>(&s_h4[0][0]);

    #pragma unroll
    for (int i = 0; i < WIN + 3; i++) {              // rows r0 .. r0+13
        U64x2 h = hp[(r0 + i) * HSTRIDE + c];        // h.a=(hx,hy), h.b=(hss,hxy)
        #pragma unroll
        for (int j = 0; j < 4; j++) {
            const int k = i - j;
            if (k >= 0 && k < WIN) {
                fma2(a01[j], h.a, gwp(k));
                fma2(a23[j], h.b, gwp(k));
            }
        }
    }

    // ---- elementwise combine + store ----
    #pragma unroll
    for (int j = 0; j < 4; j++) {
        float2 mu = unpack2(a01[j]);
        float2 e  = unpack2(a23[j]);
        float mu_x = mu.x, mu_y = mu.y;

        float mxy = mu_x * mu_y;
        float t   = mu_x * mu_x + mu_y * mu_y;
        float sxy = e.y - mxy;

        float A1 = 2.f * mxy + C1V;
        float A2 = 2.f * sxy + C2V;
        float B1 = t + C1V;
        float B2 = e.x - t + C2V;
        float ssim = __fdividef(A1 * A2, B1 * B2);

        float2 v = s_in[r0 + j + PAD][c + PAD];
        float d = v.x - v.y;
        float charb = sqrtf(fmaf(d, d, EPS2));

        float res = A_CHARB * charb + 2.0f * (d * d) + A_SSIM * (1.f - ssim);

        po[(size_t)(tile_y + r0 + j) * IMG_W + (tile_x + c)] = res;
    }
}

extern "C" void kernel_launch(void* const* d_in, const int* in_sizes, int n_in,
                              void* d_out, int out_size) {
    const float* pred = (const float*)d_in[0];
    const float* targ = (const float*)d_in[1];
    float* out = (float*)d_out;

    int planes = in_sizes[0] / (IMG_H * IMG_W);   // 48

    dim3 grid(IMG_W / TX, IMG_H / TY, planes);
    ssim_loss_kernel<<<grid, NT>>>(pred, targ, out);
}

// round 16
// speedup vs baseline: 1.3128x; 1.3128x over previous
#include <cuda_runtime.h>

#define WIN 11
#define PAD 5
#define TX 32
#define TY 32
#define INX 42
#define INY 42
#define IMG_H 512
#define IMG_W 512
#define NT 256

#define C1V 1.0e-4f
#define C2V 9.0e-4f
#define EPS2 1.0e-12f
#define A_CHARB 0.3f
#define A_SSIM  0.6f

// Normalized 11-tap Gaussian (sigma=1.5), double-precision derived.
#define W0 0.00102838f
#define W1 0.00759876f
#define W2 0.03600078f
#define W3 0.10936070f
#define W4 0.21300554f
#define W5 0.26601173f

// s_h4 row stride in float4 units — odd => H-pass STS.128 row-walk conflict-free.
#define HSTRIDE 37

typedef unsigned long long u64;

__device__ __forceinline__ float gw(int k) {   // compile-time k -> FFMA immediate
    switch (k) {
        case 0:  return W0; case 1:  return W1; case 2:  return W2;
        case 3:  return W3; case 4:  return W4; case 5:  return W5;
        case 6:  return W4; case 7:  return W3; case 8:  return W2;
        case 9:  return W1; default: return W0;
    }
}

__device__ __forceinline__ u64 gwp(int k) {    // packed (w,w) compile-time constant
    unsigned u = __float_as_uint(gw(k));
    return ((u64)u << 32) | (u64)u;
}

__device__ __forceinline__ void fma2(u64& acc, u64 a, u64 b) {
    asm("fma.rn.f32x2 %0, %1, %2, %0;" : "+l"(acc) : "l"(a), "l"(b));
}

__device__ __forceinline__ float2 unpack2(u64 v) {
    float2 t;
    asm("mov.b64 {%0, %1}, %2;" : "=f"(t.x), "=f"(t.y) : "l"(v));
    return t;
}

struct __align__(16) U64x2 { u64 a, b; };      // one LDS.128 -> two f32x2 operands

__global__ __launch_bounds__(NT, 5)
void ssim_loss_kernel(const float* __restrict__ pred,
                      const float* __restrict__ targ,
                      float* __restrict__ out) {
    __shared__ float2 s_in[INY][47];                     // (x,y); cols 42..46 zero pad
    __shared__ __align__(16) float4 s_h4[INY][HSTRIDE];  // (hx, hy, hss, hxy)

    const int tid = threadIdx.x;
    const int tile_x = blockIdx.x * TX;
    const int tile_y = blockIdx.y * TY;
    const int plane = blockIdx.z;

    const float* __restrict__ px = pred + (size_t)plane * IMG_H * IMG_W;
    const float* __restrict__ py = targ + (size_t)plane * IMG_H * IMG_W;
    float* __restrict__ po = out + (size_t)plane * IMG_H * IMG_W;

    // ---- pad-zero cols 42..46 (H window over-read region) ----
    if (tid < INY * 5) {
        int r = tid / 5, c = 42 + tid % 5;
        s_in[r][c] = make_float2(0.f, 0.f);
    }

    // ---- halo load, per-element: coalesced LDG.32 + degree-2 STS.64 ----
    // unit = r*42 + c; lanes walk columns -> LDG coalesced, STS lane stride
    // = 1 float2 (2 words) -> bank degree 2 (the 64-bit floor).
    {
        int r = tid / INX;
        int c = tid - r * INX;
        #pragma unroll
        for (int rd = 0; rd < 7; rd++) {               // 42*42 = 1764 = 6*256 + 228
            if (rd < 6 || tid < 228) {
                int gr = tile_y + r - PAD;
                int gc = tile_x + c - PAD;
                float xv = 0.f, yv = 0.f;
                if (gr >= 0 && gr < IMG_H && gc >= 0 && gc < IMG_W) {
                    int off = gr * IMG_W + gc;
                    xv = px[off];
                    yv = py[off];
                }
                s_in[r][c] = make_float2(xv, yv);
            }
            // advance by 256 = 6*42 + 4
            r += 6; c += 4;
            if (c >= INX) { c -= INX; r += 1; }
        }
    }
    __syncthreads();

    // ---- H-pass: 42 rows x 6-col chunks = 252 units, one per thread (scalar, imm weights) ----
    if (tid < INY * 6) {
        const int r  = tid % INY;
        const int c0 = (tid / INY) * 6;              // 0,6,...,30

        float ax[6], ay[6], ass[6], axy[6];
        #pragma unroll
        for (int j = 0; j < 6; j++) { ax[j]=0.f; ay[j]=0.f; ass[j]=0.f; axy[j]=0.f; }

        #pragma unroll
        for (int i = 0; i < 16; i++) {
            float2 v = s_in[r][c0 + i];
            float ss = fmaf(v.y, v.y, v.x * v.x);
            float xy = v.x * v.y;
            #pragma unroll
            for (int j = 0; j < 6; j++) {
                const int k = i - j;
                if (k >= 0 && k < WIN) {
                    const float wk = gw(k);
                    ax[j]  = fmaf(wk, v.x, ax[j]);
                    ay[j]  = fmaf(wk, v.y, ay[j]);
                    ass[j] = fmaf(wk, ss,  ass[j]);
                    axy[j] = fmaf(wk, xy,  axy[j]);
                }
            }
        }
        #pragma unroll
        for (int j = 0; j < 6; j++)
            s_h4[r][c0 + j] = make_float4(ax[j], ay[j], ass[j], axy[j]);
    }
    __syncthreads();

    // ---- V-pass: f32x2 on register pairs straight out of LDS.128 ----
    const int c  = tid & (TX - 1);
    const int r0 = (tid >> 5) * 4;                   // 0,4,...,28

    u64 a01[4], a23[4];
    #pragma unroll
    for (int j = 0; j < 4; j++) { a01[j] = 0ull; a23[j] = 0ull; }

    const U64x2* __restrict__ hp = reinterpret_cast<const U64x2*>(&s_h4[0][0]);

    #pragma unroll
    for (int i = 0; i < WIN + 3; i++) {              // rows r0 .. r0+13
        U64x2 h = hp[(r0 + i) * HSTRIDE + c];        // h.a=(hx,hy), h.b=(hss,hxy)
        #pragma unroll
        for (int j = 0; j < 4; j++) {
            const int k = i - j;
            if (k >= 0 && k < WIN) {
                fma2(a01[j], h.a, gwp(k));
                fma2(a23[j], h.b, gwp(k));
            }
        }
    }

    // ---- elementwise combine + store ----
    #pragma unroll
    for (int j = 0; j < 4; j++) {
        float2 mu = unpack2(a01[j]);
        float2 e  = unpack2(a23[j]);
        float mu_x = mu.x, mu_y = mu.y;

        float mxy = mu_x * mu_y;
        float t   = mu_x * mu_x + mu_y * mu_y;
        float sxy = e.y - mxy;

        float A1 = 2.f * mxy + C1V;
        float A2 = 2.f * sxy + C2V;
        float B1 = t + C1V;
        float B2 = e.x - t + C2V;
        float ssim = __fdividef(A1 * A2, B1 * B2);

        float2 v = s_in[r0 + j + PAD][c + PAD];
        float d = v.x - v.y;
        float charb = sqrtf(fmaf(d, d, EPS2));

        float res = A_CHARB * charb + 2.0f * (d * d) + A_SSIM * (1.f - ssim);

        po[(size_t)(tile_y + r0 + j) * IMG_W + (tile_x + c)] = res;
    }
}

extern "C" void kernel_launch(void* const* d_in, const int* in_sizes, int n_in,
                              void* d_out, int out_size) {
    const float* pred = (const float*)d_in[0];
    const float* targ = (const float*)d_in[1];
    float* out = (float*)d_out;

    int planes = in_sizes[0] / (IMG_H * IMG_W);   // 48

    dim3 grid(IMG_W / TX, IMG_H / TY, planes);
    ssim_loss_kernel<<<grid, NT>>>(pred, targ, out);
}